// round 2
// baseline (speedup 1.0000x reference)
#include <cuda_runtime.h>

#define B_  32
#define C_  256
#define T_  2048
#define K_  1024
#define N_  (B_ * T_)        // 65536 points
#define TT  128              // t-tile per block
#define KT  128              // k-tile
#define DC  64               // d-chunk (reduction dim chunk)

#define OUTQ_ELEMS ((size_t)B_ * C_ * T_)   // 16777216

// Scratch (static device globals — no allocation)
__device__ float  g_cnorm[K_];
__device__ float  g_cbT[C_ * K_];   // transposed codebook [d][k]
__device__ int    g_idx[N_];
__device__ double g_sum;

// ---------------------------------------------------------------------------
// Kernel A: codebook norms (sequential fp32, matching jnp.sum order guess),
// transposed codebook for conflict-free d-major smem tiles, zero loss scratch.
// ---------------------------------------------------------------------------
__global__ void vq_prep_kernel(const float* __restrict__ cb) {
    int k = blockIdx.x * 256 + threadIdx.x;
    if (k == 0) g_sum = 0.0;
    if (k < K_) {
        const float* row = cb + (size_t)k * C_;
        float s = 0.0f;
        for (int d = 0; d < C_; ++d) {
            float v = __ldg(row + d);
            s = __fadd_rn(s, __fmul_rn(v, v));
            g_cbT[d * K_ + k] = v;   // lanes: consecutive k -> coalesced store
        }
        g_cnorm[k] = s;
    }
}

// ---------------------------------------------------------------------------
// Packed fp32 helpers (sm_100+ f32x2 — bit-identical to two scalar fp32 FMAs)
// ---------------------------------------------------------------------------
__device__ __forceinline__ unsigned long long pack_dup(float a) {
    unsigned long long r;
    unsigned u = __float_as_uint(a);
    asm("mov.b64 %0, {%1,%1};" : "=l"(r) : "r"(u));
    return r;
}
__device__ __forceinline__ void ffma2(unsigned long long& acc,
                                      unsigned long long a,
                                      unsigned long long b) {
    asm("fma.rn.f32x2 %0, %1, %2, %0;" : "+l"(acc) : "l"(a), "l"(b));
}

// ---------------------------------------------------------------------------
// Kernel B: distance-GEMM + argmin.
// Block: one (b, t-tile of 128). Threads 256 as 16(ty,k) x 16(tx,t), 8x8 micro.
// Distances replicate reference rounding: fl( fl(sx + sc_k) - 2*dot ),
// dot = sequential fused-FMA chain over d=0..255; first-index tie-break.
// ---------------------------------------------------------------------------
__global__ __launch_bounds__(256, 1)
void vq_argmin_kernel(const float* __restrict__ in,
                      float* __restrict__ out_idx_f) {
    extern __shared__ float sm[];
    float* x_s   = sm;                    // [256][TT]  = 32768 floats
    float* cb_s  = x_s + C_ * TT;         // [DC][KT]   = 8192 floats
    float* sx_s  = cb_s + DC * KT;        // [TT]
    float* red_v = sx_s + TT;             // [16][TT]
    int*   red_k = (int*)(red_v + 16 * TT); // [16][TT]

    const int tid = threadIdx.x;
    const int b   = blockIdx.x >> 4;
    const int t0  = (blockIdx.x & 15) * TT;
    const float* xg = in + (size_t)b * C_ * T_ + t0;

    // Load X tile: [256 d][128 t], coalesced float4 along t
    for (int i = tid; i < C_ * (TT / 4); i += 256) {
        int d = i >> 5, tq = i & 31;
        float4 v = *(const float4*)(xg + (size_t)d * T_ + tq * 4);
        *(float4*)(x_s + d * TT + tq * 4) = v;
    }
    __syncthreads();

    // sx[t] = sequential fp32 sum of squares over d (replicating reference)
    if (tid < TT) {
        float s = 0.0f;
        for (int d = 0; d < C_; ++d) {
            float v = x_s[d * TT + tid];
            s = __fadd_rn(s, __fmul_rn(v, v));
        }
        sx_s[tid] = s;
    }
    __syncthreads();

    const int tx = tid & 15;   // t group
    const int ty = tid >> 4;   // k group

    float sxr[8];
#pragma unroll
    for (int j = 0; j < 8; ++j) sxr[j] = sx_s[tx * 8 + j];

    float bestv[8];
    int   bestk[8];
#pragma unroll
    for (int j = 0; j < 8; ++j) { bestv[j] = 3.4e38f; bestk[j] = 0; }

    for (int kt = 0; kt < K_ / KT; ++kt) {
        const int k0 = kt * KT;
        unsigned long long acc[8][4];
#pragma unroll
        for (int i = 0; i < 8; ++i)
#pragma unroll
            for (int j = 0; j < 4; ++j) acc[i][j] = 0ULL;

        for (int dcb = 0; dcb < C_ / DC; ++dcb) {
            const int d0 = dcb * DC;
            __syncthreads();
            // Load codebook chunk d-major from g_cbT: fully coalesced,
            // contiguous STS (conflict-free).
            for (int i = tid; i < DC * (KT / 4); i += 256) {
                int dl = i >> 5, kq = i & 31;
                float4 v = *(const float4*)(g_cbT + (size_t)(d0 + dl) * K_ + k0 + kq * 4);
                *(float4*)(cb_s + dl * KT + kq * 4) = v;
            }
            __syncthreads();

#pragma unroll 8
            for (int dd = 0; dd < DC; ++dd) {
                const int d = d0 + dd;
                // b-fragment: 8 t-values as 4 packed f32x2 (t pairs contiguous)
                const ulonglong2* brow = (const ulonglong2*)(x_s + d * TT);
                ulonglong2 u0 = brow[tx * 2];
                ulonglong2 u1 = brow[tx * 2 + 1];
                unsigned long long bp[4] = { u0.x, u0.y, u1.x, u1.y };
                // a-fragment: 8 k-values (broadcast loads, conflict-free)
                const float4* arow = (const float4*)(cb_s + dd * KT);
                float4 a01 = arow[ty * 2];
                float4 a23 = arow[ty * 2 + 1];
                float a[8] = { a01.x, a01.y, a01.z, a01.w,
                               a23.x, a23.y, a23.z, a23.w };
#pragma unroll
                for (int i = 0; i < 8; ++i) {
                    unsigned long long a2 = pack_dup(a[i]);
#pragma unroll
                    for (int j = 0; j < 4; ++j) ffma2(acc[i][j], a2, bp[j]);
                }
            }
        }

        // Epilogue for this k-tile: v = fl( fl(sx + sc) - fl(2*m) ), strict <
#pragma unroll
        for (int i = 0; i < 8; ++i) {
            const int k = k0 + ty * 8 + i;
            const float sc = g_cnorm[k];
#pragma unroll
            for (int j = 0; j < 4; ++j) {
                unsigned lo = (unsigned)(acc[i][j]);
                unsigned hi = (unsigned)(acc[i][j] >> 32);
                float m0 = __uint_as_float(lo);
                float m1 = __uint_as_float(hi);
                float t1a = __fadd_rn(sxr[2 * j], sc);
                float va  = __fsub_rn(t1a, __fmul_rn(2.0f, m0));
                if (va < bestv[2 * j]) { bestv[2 * j] = va; bestk[2 * j] = k; }
                float t1b = __fadd_rn(sxr[2 * j + 1], sc);
                float vb  = __fsub_rn(t1b, __fmul_rn(2.0f, m1));
                if (vb < bestv[2 * j + 1]) { bestv[2 * j + 1] = vb; bestk[2 * j + 1] = k; }
            }
        }
    }

    // Cross-thread reduction over the 16 ty-groups (lexicographic (v, k))
    __syncthreads();
#pragma unroll
    for (int j = 0; j < 8; ++j) {
        red_v[ty * TT + tx * 8 + j] = bestv[j];
        red_k[ty * TT + tx * 8 + j] = bestk[j];
    }
    __syncthreads();
    if (tid < TT) {
        float bv = red_v[tid];
        int   bk = red_k[tid];
        for (int r = 1; r < 16; ++r) {
            float v = red_v[r * TT + tid];
            int   k = red_k[r * TT + tid];
            if (v < bv || (v == bv && k < bk)) { bv = v; bk = k; }
        }
        int n = b * T_ + t0 + tid;
        g_idx[n] = bk;
        out_idx_f[n] = (float)bk;
    }
}

// ---------------------------------------------------------------------------
// Kernel C: gather codebook rows -> smem (coalesced, conflict-free via pad 257),
// write quantized output [B,C,T] coalesced, accumulate loss in double.
// ---------------------------------------------------------------------------
__global__ __launch_bounds__(256, 1)
void vq_scatter_kernel(const float* __restrict__ in,
                       const float* __restrict__ cb,
                       float* __restrict__ out_q) {
    extern __shared__ float sm[];
    float*  q_s  = sm;                          // [128][257]
    double* rsum = (double*)(sm + TT * 257);    // [256]
    __shared__ int idx_s[TT];

    const int tid = threadIdx.x;
    const int b   = blockIdx.x >> 4;
    const int t0  = (blockIdx.x & 15) * TT;

    if (tid < TT) idx_s[tid] = g_idx[b * T_ + t0 + tid];
    __syncthreads();

    // Stage the 128 needed codebook rows: global reads coalesced, STS stride-1
    for (int i = tid; i < TT * C_; i += 256) {
        int r = i >> 8, c = i & 255;
        q_s[r * 257 + c] = __ldg(cb + (size_t)idx_s[r] * C_ + c);
    }
    __syncthreads();

    double lsum = 0.0;
    for (int i = tid; i < TT * C_; i += 256) {
        int cc = i >> 7, t = i & 127;
        size_t off = ((size_t)b * C_ + cc) * T_ + t0 + t;
        float q  = q_s[t * 257 + cc];     // stride 257 -> conflict-free
        float xv = in[off];
        out_q[off] = q;                   // quantized_st value == quantized
        float d = __fsub_rn(q, xv);
        lsum += (double)(__fmul_rn(d, d));
    }

    rsum[tid] = lsum;
    __syncthreads();
    for (int s = 128; s > 0; s >>= 1) {
        if (tid < s) rsum[tid] += rsum[tid + s];
        __syncthreads();
    }
    if (tid == 0) atomicAdd(&g_sum, rsum[0]);
}

// ---------------------------------------------------------------------------
// Kernel D: loss = q_latent + 0.25 * e_latent = 1.25 * mean((q - x)^2)
// ---------------------------------------------------------------------------
__global__ void vq_loss_kernel(float* __restrict__ out_loss) {
    out_loss[0] = (float)(1.25 * g_sum / (double)OUTQ_ELEMS);
}

// ---------------------------------------------------------------------------
extern "C" void kernel_launch(void* const* d_in, const int* in_sizes, int n_in,
                              void* d_out, int out_size) {
    const float* in = (const float*)d_in[0];
    const float* cb = (const float*)d_in[1];
    if (n_in >= 2 && in_sizes[0] == K_ * C_) {  // defensive input-order check
        const float* t = in; in = cb; cb = t;
    }

    float* out      = (float*)d_out;
    float* out_q    = out;                         // [B, C, T]
    float* out_loss = out + OUTQ_ELEMS;            // scalar
    float* out_idx  = out_loss + 1;                // [B, T] as float

    const int SMEM_B = (C_ * TT + DC * KT + TT + 16 * TT) * 4 + 16 * TT * 4; // 180736
    const int SMEM_C = TT * 257 * 4 + 256 * 8;                               // 133632
    cudaFuncSetAttribute(vq_argmin_kernel,
                         cudaFuncAttributeMaxDynamicSharedMemorySize, SMEM_B);
    cudaFuncSetAttribute(vq_scatter_kernel,
                         cudaFuncAttributeMaxDynamicSharedMemorySize, SMEM_C);

    vq_prep_kernel<<<4, 256>>>(cb);
    vq_argmin_kernel<<<512, 256, SMEM_B>>>(in, out_idx);
    vq_scatter_kernel<<<512, 256, SMEM_C>>>(in, cb, out_q);
    vq_loss_kernel<<<1, 1>>>(out_loss);
}